// round 1
// baseline (speedup 1.0000x reference)
#include <cuda_runtime.h>
#include <math_constants.h>

// Problem constants
#define NTOK   65536     // 64*32*32 tokens
#define EDIM   256
#define NCODE  1024
#define BM     128
#define BN     128
#define BK     16

// Static device scratch (no runtime allocation allowed)
__device__ float XT_g[EDIM * NTOK];        // x transposed: [D][N]  (64 MB)
__device__ float ET_g[EDIM * NCODE];       // codebook transposed: [D][K] (1 MB)
__device__ float enorm_g[NCODE];           // ||e_k||^2
__device__ int   bestIdx_g[NTOK];          // argmin index per token
__device__ float lossAccum_g;              // sum of (q-x)^2

// ---------------------------------------------------------------------------
__global__ void init_kernel() { lossAccum_g = 0.0f; }

// Generic 32x32 tiled transpose into one of the two static outputs.
// R,C multiples of 32. out[c*R + r] = in[r*C + c].
__global__ void transpose_kernel(const float* __restrict__ in, int R, int C, int which) {
    __shared__ float tile[32][33];
    float* out = which ? ET_g : XT_g;
    int c0 = blockIdx.x * 32, r0 = blockIdx.y * 32;
    int tx = threadIdx.x, ty = threadIdx.y;   // block (32,8)
#pragma unroll
    for (int dy = 0; dy < 32; dy += 8)
        tile[ty + dy][tx] = in[(size_t)(r0 + ty + dy) * C + (c0 + tx)];
    __syncthreads();
#pragma unroll
    for (int dy = 0; dy < 32; dy += 8)
        out[(size_t)(c0 + ty + dy) * R + (r0 + tx)] = tile[tx][ty + dy];
}

// One warp per codebook row: ||e||^2
__global__ void enorm_kernel(const float* __restrict__ cb) {
    int code = blockIdx.x * 8 + (threadIdx.x >> 5);
    int lane = threadIdx.x & 31;
    const float* e = cb + (size_t)code * EDIM;
    float s = 0.0f;
#pragma unroll
    for (int i = lane; i < EDIM; i += 32) { float v = e[i]; s = fmaf(v, v, s); }
#pragma unroll
    for (int off = 16; off; off >>= 1) s += __shfl_xor_sync(0xffffffffu, s, off);
    if (lane == 0) enorm_g[code] = s;
}

// ---------------------------------------------------------------------------
// Main fused GEMM + argmin.
// Block: 128 rows (tokens) x all 1024 codes. 256 threads, 8x8 micro-tile each.
// Thread map: tx = t&15 (cols), ty = t>>4 (rows).
//   rows:  ty*4+i (i<4), 64+ty*4+(i-4) (i>=4)
//   cols:  tx*4+j (j<4), 64+tx*4+(j-4) (j>=4)
// The 16 threads that share a row form one half-warp -> butterfly shuffle reduce.
__global__ __launch_bounds__(256, 2) void vq_argmin_kernel() {
    __shared__ float4 Xs[2][BK][BM / 4];   // 16 KB
    __shared__ float4 Es[2][BK][BN / 4];   // 16 KB
    const int t  = threadIdx.x;
    const int tx = t & 15, ty = t >> 4;
    const int r0 = blockIdx.x * BM;

    float bestd[8];
    int   besti[8];
#pragma unroll
    for (int i = 0; i < 8; i++) { bestd[i] = CUDART_INF_F; besti[i] = 0; }

    for (int nt = 0; nt < NCODE / BN; nt++) {
        const int c0 = nt * BN;
        float acc[8][8];
#pragma unroll
        for (int i = 0; i < 8; i++)
#pragma unroll
            for (int j = 0; j < 8; j++) acc[i][j] = 0.0f;

        // prefetch chunk 0 into registers
        float4 px[2], pe[2];
#pragma unroll
        for (int q = 0; q < 2; q++) {
            int lin = t + q * 256, kl = lin >> 5, c4 = lin & 31;
            px[q] = *(const float4*)&XT_g[(size_t)kl * NTOK + r0 + c4 * 4];
            pe[q] = *(const float4*)&ET_g[(size_t)kl * NCODE + c0 + c4 * 4];
        }

        int buf = 0;
        for (int kc = 0; kc < EDIM; kc += BK) {
            // stage registers -> smem (ping-pong: one sync/iter is sufficient)
#pragma unroll
            for (int q = 0; q < 2; q++) {
                int lin = t + q * 256, kl = lin >> 5, c4 = lin & 31;
                Xs[buf][kl][c4] = px[q];
                Es[buf][kl][c4] = pe[q];
            }
            __syncthreads();
            if (kc + BK < EDIM) {
#pragma unroll
                for (int q = 0; q < 2; q++) {
                    int lin = t + q * 256, kl = lin >> 5, c4 = lin & 31;
                    px[q] = *(const float4*)&XT_g[(size_t)(kc + BK + kl) * NTOK + r0 + c4 * 4];
                    pe[q] = *(const float4*)&ET_g[(size_t)(kc + BK + kl) * NCODE + c0 + c4 * 4];
                }
            }
#pragma unroll
            for (int kk = 0; kk < BK; kk++) {
                float4 a0 = Xs[buf][kk][ty],     a1 = Xs[buf][kk][16 + ty];
                float4 b0 = Es[buf][kk][tx],     b1 = Es[buf][kk][16 + tx];
                float a[8] = {a0.x, a0.y, a0.z, a0.w, a1.x, a1.y, a1.z, a1.w};
                float b[8] = {b0.x, b0.y, b0.z, b0.w, b1.x, b1.y, b1.z, b1.w};
#pragma unroll
                for (int i = 0; i < 8; i++)
#pragma unroll
                    for (int j = 0; j < 8; j++)
                        acc[i][j] = fmaf(a[i], b[j], acc[i][j]);
            }
            buf ^= 1;
        }
        __syncthreads();   // before next tile reuses the smem buffers

        // per-tile argmin of ||e||^2 - 2 x.e  (|x|^2 row-constant, irrelevant)
#pragma unroll
        for (int i = 0; i < 8; i++) {
            float mind = CUDART_INF_F;
            int   mini = 0;
#pragma unroll
            for (int j = 0; j < 8; j++) {
                int col = c0 + ((j < 4) ? tx * 4 + j : 64 + tx * 4 + (j - 4));
                float dist = __ldg(&enorm_g[col]) - 2.0f * acc[i][j];
                if (dist < mind) { mind = dist; mini = col; }   // cols ascending in j -> first-wins
            }
            // reduce over the 16 lanes sharing this row (half-warp butterfly)
#pragma unroll
            for (int off = 8; off; off >>= 1) {
                float od = __shfl_xor_sync(0xffffffffu, mind, off);
                int   oi = __shfl_xor_sync(0xffffffffu, mini, off);
                if (od < mind || (od == mind && oi < mini)) { mind = od; mini = oi; }
            }
            if (mind < bestd[i] || (mind == bestd[i] && mini < besti[i])) {
                bestd[i] = mind; besti[i] = mini;
            }
        }
    }

    if (tx == 0) {
#pragma unroll
        for (int i = 0; i < 8; i++) {
            int rloc = (i < 4) ? ty * 4 + i : 64 + ty * 4 + (i - 4);
            bestIdx_g[r0 + rloc] = besti[i];
        }
    }
}

// ---------------------------------------------------------------------------
// Gather quantized = codebook[idx], accumulate sum((q-x)^2). One warp per row.
__global__ void vq_gather_kernel(const float* __restrict__ x,
                                 const float* __restrict__ cb,
                                 float* __restrict__ out) {
    __shared__ float warpsum[8];
    int w = threadIdx.x >> 5, lane = threadIdx.x & 31;
    int row = blockIdx.x * 8 + w;
    int idx = bestIdx_g[row];
    const float4* q  = (const float4*)(cb + (size_t)idx * EDIM);
    const float4* xr = (const float4*)(x + (size_t)row * EDIM);
    float4*       o  = (float4*)(out + (size_t)row * EDIM);
    float s = 0.0f;
#pragma unroll
    for (int i = lane; i < EDIM / 4; i += 32) {
        float4 qv = q[i], xv = xr[i];
        o[i] = qv;
        float dx = qv.x - xv.x, dy = qv.y - xv.y, dz = qv.z - xv.z, dw = qv.w - xv.w;
        s += dx * dx + dy * dy + dz * dz + dw * dw;
    }
#pragma unroll
    for (int off = 16; off; off >>= 1) s += __shfl_xor_sync(0xffffffffu, s, off);
    if (lane == 0) warpsum[w] = s;
    __syncthreads();
    if (threadIdx.x == 0) {
        float bs = 0.0f;
#pragma unroll
        for (int i = 0; i < 8; i++) bs += warpsum[i];
        atomicAdd(&lossAccum_g, bs);
    }
}

__global__ void finalize_kernel(float* __restrict__ out, int loss_off) {
    out[loss_off] = 1.25f * lossAccum_g / 16777216.0f;
}

// ---------------------------------------------------------------------------
extern "C" void kernel_launch(void* const* d_in, const int* in_sizes, int n_in,
                              void* d_out, int out_size) {
    const float* x  = (const float*)d_in[0];
    const float* cb = (const float*)d_in[1];
    // robustness: detect swapped input order by element counts
    if (n_in >= 2 && in_sizes[0] == NCODE * EDIM && in_sizes[1] == NTOK * EDIM) {
        const float* tmp = x; x = cb; cb = tmp;
    }
    float* out = (float*)d_out;

    init_kernel<<<1, 1>>>();
    transpose_kernel<<<dim3(EDIM / 32, NTOK / 32), dim3(32, 8)>>>(x,  NTOK,  EDIM, 0);
    transpose_kernel<<<dim3(EDIM / 32, NCODE / 32), dim3(32, 8)>>>(cb, NCODE, EDIM, 1);
    enorm_kernel<<<NCODE / 8, 256>>>(cb);
    vq_argmin_kernel<<<NTOK / BM, 256>>>();
    vq_gather_kernel<<<NTOK / 8, 256>>>(x, cb, out);
    finalize_kernel<<<1, 1>>>(out, out_size - 1);
}

// round 3
// speedup vs baseline: 3.8639x; 3.8639x over previous
#include <cuda_runtime.h>
#include <cuda_fp16.h>
#include <math_constants.h>
#include <cstdint>

#define NTOK   65536
#define EDIM   256
#define NCODE  1024
#define BM     128
#define BN     128
#define NT_CNT (NCODE / BN)          // 8 B tiles
#define STRIDE 264                   // halves per smem row (256 + 8 pad -> conflict-free LDSM)

// ---- static device scratch ----
__device__ __half AH[(size_t)NTOK * EDIM];    // 32 MB fp16 x
__device__ __half EH[(size_t)NCODE * EDIM];   // 0.5 MB fp16 codebook
__device__ float enorm_g[NCODE];
__device__ int   bestIdx_g[NTOK];
__device__ int   bestIdx2_g[NTOK];
__device__ float lossAccum_g;

// smem layout (bytes)
#define SM_A      0u
#define SM_B(s)   (67584u + (s) * 67584u)     // 128*264*2 each
#define SM_EN     202752u                     // 1024 floats
#define SM_MERGE  206848u                     // [2][128] * 16B
#define SMEM_SZ   210944

// ---------------------------------------------------------------------------
__device__ __forceinline__ uint32_t smem_u32(const void* p) {
    uint32_t a;
    asm("{ .reg .u64 t; cvta.to.shared.u64 t, %1; cvt.u32.u64 %0, t; }" : "=r"(a) : "l"(p));
    return a;
}
__device__ __forceinline__ void cpasync16(uint32_t dst, const void* src) {
    asm volatile("cp.async.cg.shared.global [%0], [%1], 16;" :: "r"(dst), "l"(src) : "memory");
}
#define CP_COMMIT()  asm volatile("cp.async.commit_group;" ::: "memory")
#define CP_WAIT(n)   asm volatile("cp.async.wait_group %0;" :: "n"(n) : "memory")

__device__ __forceinline__ void ldm_x4(uint32_t* r, uint32_t addr) {
    asm volatile("ldmatrix.sync.aligned.m8n8.x4.shared.b16 {%0,%1,%2,%3}, [%4];"
        : "=r"(r[0]), "=r"(r[1]), "=r"(r[2]), "=r"(r[3]) : "r"(addr));
}
__device__ __forceinline__ void mma16816(float* c, const uint32_t* a, uint32_t b0, uint32_t b1) {
    asm volatile("mma.sync.aligned.m16n8k16.row.col.f32.f16.f16.f32 "
        "{%0,%1,%2,%3}, {%4,%5,%6,%7}, {%8,%9}, {%0,%1,%2,%3};"
        : "+f"(c[0]), "+f"(c[1]), "+f"(c[2]), "+f"(c[3])
        : "r"(a[0]), "r"(a[1]), "r"(a[2]), "r"(a[3]), "r"(b0), "r"(b1));
}

// ---------------------------------------------------------------------------
__global__ void init_kernel() { lossAccum_g = 0.0f; }

__global__ void pack_half_kernel(const float* __restrict__ in, __half* __restrict__ out,
                                 int n4) {
    int gid = blockIdx.x * blockDim.x + threadIdx.x;
    if (gid >= n4) return;
    float4 v = *(const float4*)(in + (size_t)gid * 4);
    __half h[4] = { __float2half_rn(v.x), __float2half_rn(v.y),
                    __float2half_rn(v.z), __float2half_rn(v.w) };
    *(uint2*)(out + (size_t)gid * 4) = *(uint2*)h;
}

__global__ void enorm_kernel(const float* __restrict__ cb) {
    int code = blockIdx.x * 8 + (threadIdx.x >> 5);
    int lane = threadIdx.x & 31;
    const float* e = cb + (size_t)code * EDIM;
    float s = 0.0f;
#pragma unroll
    for (int i = lane; i < EDIM; i += 32) { float v = e[i]; s = fmaf(v, v, s); }
#pragma unroll
    for (int off = 16; off; off >>= 1) s += __shfl_xor_sync(0xffffffffu, s, off);
    if (lane == 0) enorm_g[code] = s;
}

// ---------------------------------------------------------------------------
// Main HMMA kernel. CTA: 256 threads = warp grid 4(M) x 2(N).
// Warp tile: 32(M) x 64(N). Thread accums: 2 m-tiles x 8 n-tiles x 4 = 64 fp32.
__global__ __launch_bounds__(256, 1) void vq_mma_kernel() {
    extern __shared__ char smem[];
    const uint32_t sb = smem_u32(smem);
    const int tid = threadIdx.x, lane = tid & 31, wid = tid >> 5;
    const int wy = wid >> 1, wx = wid & 1;            // warp coords: 4 x 2
    const int r0 = blockIdx.x * BM;

    // stage enorm into smem
#pragma unroll
    for (int i = 0; i < 4; i++)
        ((float*)(smem + SM_EN))[tid + i * 256] = enorm_g[tid + i * 256];

    const char* Agl = (const char*)AH + (size_t)r0 * EDIM * 2;
    const char* Bgl = (const char*)EH;

    // load A tile (128 x 256 halves) + B tile nt into stage s
    auto load_A = [&]() {
#pragma unroll
        for (int j = 0; j < 16; j++) {
            int i = tid + j * 256;                 // 4096 chunks of 16B
            int row = i >> 5, ch = i & 31;
            cpasync16(sb + SM_A + (uint32_t)row * (STRIDE * 2) + ch * 16,
                      Agl + (size_t)row * 512 + ch * 16);
        }
    };
    auto load_B = [&](int nt, int s) {
        const char* Bp = Bgl + (size_t)nt * BN * EDIM * 2;
#pragma unroll
        for (int j = 0; j < 16; j++) {
            int i = tid + j * 256;
            int row = i >> 5, ch = i & 31;
            cpasync16(sb + SM_B(s) + (uint32_t)row * (STRIDE * 2) + ch * 16,
                      Bp + (size_t)row * 512 + ch * 16);
        }
    };

    load_A(); load_B(0, 0); CP_COMMIT();
    load_B(1, 1); CP_COMMIT();

    // per-thread lane-invariant ldmatrix offsets
    const uint32_t aoff = (uint32_t)(lane & 15) * (STRIDE * 2) + ((lane >> 4) << 4);
    const uint32_t boff = (uint32_t)(((lane >> 4) << 3) + (lane & 7)) * (STRIDE * 2)
                        + ((lane & 8) << 1);

    // top-2 state: 4 row-slots (mt*2 + upper)
    float td0[4], td1[4]; int ti0[4], ti1[4];
#pragma unroll
    for (int s = 0; s < 4; s++) { td0[s] = td1[s] = CUDART_INF_F; ti0[s] = ti1[s] = 0; }

    for (int nt = 0; nt < NT_CNT; nt++) {
        if (nt < NT_CNT - 1) { CP_WAIT(1); } else { CP_WAIT(0); }
        __syncthreads();

        const int s = nt & 1;
        const uint32_t Ab = sb + SM_A + (uint32_t)(wy * 32) * (STRIDE * 2) + aoff;
        const uint32_t Bb = sb + SM_B(s) + (uint32_t)(wx * 64) * (STRIDE * 2) + boff;

        float acc[2][8][4];
#pragma unroll
        for (int mt = 0; mt < 2; mt++)
#pragma unroll
            for (int n8 = 0; n8 < 8; n8++)
#pragma unroll
                for (int k = 0; k < 4; k++) acc[mt][n8][k] = 0.0f;

#pragma unroll
        for (int ks = 0; ks < 16; ks++) {
            uint32_t af[2][4], bf[4][4];
#pragma unroll
            for (int mt = 0; mt < 2; mt++)
                ldm_x4(af[mt], Ab + (uint32_t)(mt * 16) * (STRIDE * 2) + ks * 32);
#pragma unroll
            for (int g = 0; g < 4; g++)
                ldm_x4(bf[g], Bb + (uint32_t)(g * 16) * (STRIDE * 2) + ks * 32);
#pragma unroll
            for (int mt = 0; mt < 2; mt++)
#pragma unroll
                for (int n8 = 0; n8 < 8; n8++) {
                    int g = n8 >> 1, t = n8 & 1;
                    mma16816(acc[mt][n8], af[mt], bf[g][t ? 2 : 0], bf[g][t ? 3 : 1]);
                }
        }

        // epilogue: d = ||e||^2 - 2 x.e ; per-thread top-2 per row-slot
        const float* en = (const float*)(smem + SM_EN);
        const int cbase = nt * BN + wx * 64 + 2 * (lane & 3);
#pragma unroll
        for (int mt = 0; mt < 2; mt++)
#pragma unroll
            for (int n8 = 0; n8 < 8; n8++) {
#pragma unroll
                for (int u = 0; u < 2; u++) {          // u=0: c0c1 (row l/4), u=1: c2c3 (row+8)
                    int slot = mt * 2 + u;
#pragma unroll
                    for (int p = 0; p < 2; p++) {
                        int col = cbase + n8 * 8 + p;
                        float d = en[col] - 2.0f * acc[mt][n8][u * 2 + p];
                        if (d < td0[slot]) { td1[slot] = td0[slot]; ti1[slot] = ti0[slot];
                                             td0[slot] = d; ti0[slot] = col; }
                        else if (d < td1[slot]) { td1[slot] = d; ti1[slot] = col; }
                    }
                }
            }

        __syncthreads();
        if (nt + 2 < NT_CNT) { load_B(nt + 2, s); CP_COMMIT(); }
    }

    // merge top-2 across the 4 lanes sharing a row (lane & 3)
#pragma unroll
    for (int slot = 0; slot < 4; slot++) {
#pragma unroll
        for (int off = 1; off <= 2; off <<= 1) {
            float e0 = __shfl_xor_sync(0xffffffffu, td0[slot], off);
            float e1 = __shfl_xor_sync(0xffffffffu, td1[slot], off);
            int   j0 = __shfl_xor_sync(0xffffffffu, ti0[slot], off);
            int   j1 = __shfl_xor_sync(0xffffffffu, ti1[slot], off);
            // merge (td0,ti0,td1,ti1) with (e0,j0,e1,j1)
            float d0 = td0[slot], d1 = td1[slot]; int i0 = ti0[slot], i1 = ti1[slot];
            bool efirst = (e0 < d0) || (e0 == d0 && j0 < i0);
            float w0 = efirst ? e0 : d0;  int w0i = efirst ? j0 : i0;
            float lo = efirst ? d0 : e0;  int loi = efirst ? i0 : j0;
            float w1 = efirst ? e1 : d1;  int w1i = efirst ? j1 : i1;
            bool secl = (lo < w1) || (lo == w1 && loi < w1i);
            td0[slot] = w0; ti0[slot] = w0i;
            td1[slot] = secl ? lo : w1; ti1[slot] = secl ? loi : w1i;
        }
    }
    // lane&3==0 holds rows: wy*32 + mt*16 + (lane>>2) + u*8
    if ((lane & 3) == 0) {
#pragma unroll
        for (int slot = 0; slot < 4; slot++) {
            int mt = slot >> 1, u = slot & 1;
            int r = wy * 32 + mt * 16 + (lane >> 2) + u * 8;
            float4* mb = (float4*)(smem + SM_MERGE) + wx * 128 + r;
            float4 v; v.x = td0[slot]; v.y = td1[slot];
            v.z = __int_as_float(ti0[slot]); v.w = __int_as_float(ti1[slot]);
            *mb = v;
        }
    }
    __syncthreads();
    if (tid < 128) {
        float4 a = ((float4*)(smem + SM_MERGE))[tid];
        float4 b = ((float4*)(smem + SM_MERGE))[128 + tid];
        float ad0 = a.x, ad1 = a.y; int ai0 = __float_as_int(a.z), ai1 = __float_as_int(a.w);
        float bd0 = b.x, bd1 = b.y; int bi0 = __float_as_int(b.z), bi1 = __float_as_int(b.w);
        bool bfirst = (bd0 < ad0) || (bd0 == ad0 && bi0 < ai0);
        float w0 = bfirst ? bd0 : ad0;  int w0i = bfirst ? bi0 : ai0;
        float lo = bfirst ? ad0 : bd0;  int loi = bfirst ? ai0 : bi0;
        float w1 = bfirst ? bd1 : ad1;  int w1i = bfirst ? bi1 : ai1;
        bool secl = (lo < w1) || (lo == w1 && loi < w1i);
        bestIdx_g[r0 + tid]  = w0i;
        bestIdx2_g[r0 + tid] = secl ? loi : w1i;
        (void)w0;
    }
}

// ---------------------------------------------------------------------------
// Exact fp32 rescore of top-2 + gather + loss. One warp per row.
__global__ void vq_gather_kernel(const float* __restrict__ x,
                                 const float* __restrict__ cb,
                                 float* __restrict__ out) {
    __shared__ float warpsum[8];
    int w = threadIdx.x >> 5, lane = threadIdx.x & 31;
    int row = blockIdx.x * 8 + w;
    int c0 = bestIdx_g[row], c1 = bestIdx2_g[row];
    const float4* xr = (const float4*)(x + (size_t)row * EDIM);
    const float4* e0 = (const float4*)(cb + (size_t)c0 * EDIM);
    const float4* e1 = (const float4*)(cb + (size_t)c1 * EDIM);
    float4 xv[2], v0[2], v1[2];
    float dot0 = 0.0f, dot1 = 0.0f;
#pragma unroll
    for (int t = 0; t < 2; t++) {
        int i = lane + t * 32;
        xv[t] = xr[i]; v0[t] = e0[i]; v1[t] = e1[i];
        dot0 += xv[t].x * v0[t].x + xv[t].y * v0[t].y + xv[t].z * v0[t].z + xv[t].w * v0[t].w;
        dot1 += xv[t].x * v1[t].x + xv[t].y * v1[t].y + xv[t].z * v1[t].z + xv[t].w * v1[t].w;
    }
#pragma unroll
    for (int off = 16; off; off >>= 1) {
        dot0 += __shfl_xor_sync(0xffffffffu, dot0, off);
        dot1 += __shfl_xor_sync(0xffffffffu, dot1, off);
    }
    float d0 = __ldg(&enorm_g[c0]) - 2.0f * dot0;
    float d1 = __ldg(&enorm_g[c1]) - 2.0f * dot1;
    bool take1 = (d1 < d0) || (d1 == d0 && c1 < c0);

    float4* o = (float4*)(out + (size_t)row * EDIM);
    float s = 0.0f;
#pragma unroll
    for (int t = 0; t < 2; t++) {
        float4 q = take1 ? v1[t] : v0[t];
        o[lane + t * 32] = q;
        float dx = q.x - xv[t].x, dy = q.y - xv[t].y, dz = q.z - xv[t].z, dw = q.w - xv[t].w;
        s += dx * dx + dy * dy + dz * dz + dw * dw;
    }
#pragma unroll
    for (int off = 16; off; off >>= 1) s += __shfl_xor_sync(0xffffffffu, s, off);
    if (lane == 0) warpsum[w] = s;
    __syncthreads();
    if (threadIdx.x == 0) {
        float bs = 0.0f;
#pragma unroll
        for (int i = 0; i < 8; i++) bs += warpsum[i];
        atomicAdd(&lossAccum_g, bs);
    }
}

__global__ void finalize_kernel(float* __restrict__ out, int loss_off) {
    out[loss_off] = 1.25f * lossAccum_g / 16777216.0f;
}

// ---------------------------------------------------------------------------
extern "C" void kernel_launch(void* const* d_in, const int* in_sizes, int n_in,
                              void* d_out, int out_size) {
    const float* x  = (const float*)d_in[0];
    const float* cb = (const float*)d_in[1];
    if (n_in >= 2 && in_sizes[0] == NCODE * EDIM && in_sizes[1] == NTOK * EDIM) {
        const float* t = x; x = cb; cb = t;
    }
    float* out = (float*)d_out;

    static int smem_set = 0;
    if (!smem_set) {
        cudaFuncSetAttribute(vq_mma_kernel, cudaFuncAttributeMaxDynamicSharedMemorySize, SMEM_SZ);
        smem_set = 1;
    }

    __half *ah, *eh;
    cudaGetSymbolAddress((void**)&ah, AH);
    cudaGetSymbolAddress((void**)&eh, EH);

    init_kernel<<<1, 1>>>();
    pack_half_kernel<<<(NTOK * EDIM / 4 + 255) / 256, 256>>>(x, ah, NTOK * EDIM / 4);
    pack_half_kernel<<<(NCODE * EDIM / 4 + 255) / 256, 256>>>(cb, eh, NCODE * EDIM / 4);
    enorm_kernel<<<NCODE / 8, 256>>>(cb);
    vq_mma_kernel<<<NTOK / BM, 256, SMEM_SZ>>>();
    vq_gather_kernel<<<NTOK / 8, 256>>>(x, cb, out);
    finalize_kernel<<<1, 1>>>(out, out_size - 1);
}